// round 2
// baseline (speedup 1.0000x reference)
#include <cuda_runtime.h>
#include <cstdint>

// SGIntoKGPool: out[b,m,c] = (sum_n adj[b,n,m] * x[b,c,n]) / max(sum_n adj[b,n,m], 1)
// B=8, C=64, N=4096, M=2048.
// Round 2: split-K (2-way over N) for 2 CTAs/SM occupancy + pre-duplicated X in smem
// (no per-k MOVs). fp32 FFMA2 (packed fma.rn.f32x2) GEMM, fused degrees, combine kernel.

#define BZv 8
#define Cv  64
#define Nv  4096
#define Mv  2048
#define MT  128      // m-tile per block
#define KS  16       // k-tile
#define NSPLIT 2
#define TPB  (Nv / KS / NSPLIT)   // 128 tiles per block
#define XST  66      // XsD row stride in ull (padded)

typedef unsigned long long ull;

// scratch: partial GEMM results and degrees per split
__device__ float g_part[NSPLIT * BZv * Mv * Cv];   // 8 MB
__device__ float g_deg [NSPLIT * BZv * Mv];        // 128 KB

__device__ __forceinline__ ull rep2(float x) {
    ull r; asm("mov.b64 %0, {%1, %1};" : "=l"(r) : "f"(x)); return r;
}
__device__ __forceinline__ void fma2(ull &d, ull a, ull b) {
    asm("fma.rn.f32x2 %0, %1, %2, %0;" : "+l"(d) : "l"(a), "l"(b));
}
__device__ __forceinline__ void add2(ull &d, ull a) {
    asm("add.rn.f32x2 %0, %0, %1;" : "+l"(d) : "l"(a));
}
__device__ __forceinline__ float lo32(ull v) { return __uint_as_float((unsigned)(v & 0xffffffffull)); }
__device__ __forceinline__ float hi32(ull v) { return __uint_as_float((unsigned)(v >> 32)); }

__global__ __launch_bounds__(256, 2)
void sg_kg_pool_main(const float* __restrict__ x,    // (B, C, N)
                     const float* __restrict__ adj)  // (B, N, M)
{
    __shared__ float As[2][KS * MT];     // A tile [k][m]   8KB x2
    __shared__ ull   XsD[2][KS * XST];   // X tile [k][c] duplicated f32x2, padded
    __shared__ float degS[KS * MT];      // degree partials [ty][m]

    const int b   = blockIdx.y;
    const int s   = blockIdx.z;          // K split index
    const int m0  = blockIdx.x * MT;
    const int tid = threadIdx.x;
    const int tx  = tid & 15;   // m direction (16)
    const int ty  = tid >> 4;   // c direction (16)

    const float* Ab = adj + (size_t)b * Nv * Mv + (size_t)s * (Nv / NSPLIT) * Mv + m0;
    const float* Xb = x   + (size_t)b * Cv * Nv + (size_t)s * (Nv / NSPLIT);

    // global-load lane mapping
    const int arow = tid >> 5;         // rows arow, arow+8 of the 16-row A tile
    const int acol = (tid & 31) * 4;
    const int xc   = tid >> 2;         // 0..63 (c)
    const int xq   = (tid & 3) * 4;    // k offset within tile

    ull acc[4][4];
    #pragma unroll
    for (int p = 0; p < 4; p++)
        #pragma unroll
        for (int cc = 0; cc < 4; cc++) acc[p][cc] = 0ull;
    ull dacc[4] = {0ull, 0ull, 0ull, 0ull};

    // ---- prologue: tile 0 ----
    float4 pa0 = *(const float4*)(Ab + (size_t)arow       * Mv + acol);
    float4 pa1 = *(const float4*)(Ab + (size_t)(arow + 8) * Mv + acol);
    float4 pxv = *(const float4*)(Xb + (size_t)xc * Nv + xq);

    *(float4*)&As[0][arow * MT + acol]       = pa0;
    *(float4*)&As[0][(arow + 8) * MT + acol] = pa1;
    XsD[0][(xq + 0) * XST + xc] = rep2(pxv.x);
    XsD[0][(xq + 1) * XST + xc] = rep2(pxv.y);
    XsD[0][(xq + 2) * XST + xc] = rep2(pxv.z);
    XsD[0][(xq + 3) * XST + xc] = rep2(pxv.w);
    __syncthreads();

    int cur = 0;
    for (int t = 0; t < TPB; t++) {
        // register prefetch of next tile
        if (t + 1 < TPB) {
            const float* An = Ab + (size_t)(t + 1) * KS * Mv;
            pa0 = *(const float4*)(An + (size_t)arow       * Mv + acol);
            pa1 = *(const float4*)(An + (size_t)(arow + 8) * Mv + acol);
            pxv = *(const float4*)(Xb + (size_t)xc * Nv + (t + 1) * KS + xq);
        }

        const float* Ac = As[cur];
        const ull*   Xc = XsD[cur];

        // fused degree slice: sum adj row k_local = ty of this tile
        {
            ulonglong2 d0 = *(const ulonglong2*)(Ac + ty * MT + tx * 4);
            ulonglong2 d1 = *(const ulonglong2*)(Ac + ty * MT + 64 + tx * 4);
            add2(dacc[0], d0.x); add2(dacc[1], d0.y);
            add2(dacc[2], d1.x); add2(dacc[3], d1.y);
        }

        #pragma unroll
        for (int k = 0; k < KS; k++) {
            ulonglong2 a0 = *(const ulonglong2*)(Ac + k * MT + tx * 4);
            ulonglong2 a1 = *(const ulonglong2*)(Ac + k * MT + 64 + tx * 4);
            ulonglong2 x01 = *(const ulonglong2*)(Xc + k * XST + ty * 4);
            ulonglong2 x23 = *(const ulonglong2*)(Xc + k * XST + ty * 4 + 2);
            ull ap0 = a0.x, ap1 = a0.y, ap2 = a1.x, ap3 = a1.y;
            fma2(acc[0][0], ap0, x01.x); fma2(acc[0][1], ap0, x01.y);
            fma2(acc[0][2], ap0, x23.x); fma2(acc[0][3], ap0, x23.y);
            fma2(acc[1][0], ap1, x01.x); fma2(acc[1][1], ap1, x01.y);
            fma2(acc[1][2], ap1, x23.x); fma2(acc[1][3], ap1, x23.y);
            fma2(acc[2][0], ap2, x01.x); fma2(acc[2][1], ap2, x01.y);
            fma2(acc[2][2], ap2, x23.x); fma2(acc[2][3], ap2, x23.y);
            fma2(acc[3][0], ap3, x01.x); fma2(acc[3][1], ap3, x01.y);
            fma2(acc[3][2], ap3, x23.x); fma2(acc[3][3], ap3, x23.y);
        }

        if (t + 1 < TPB) {
            int nxt = cur ^ 1;
            *(float4*)&As[nxt][arow * MT + acol]       = pa0;
            *(float4*)&As[nxt][(arow + 8) * MT + acol] = pa1;
            XsD[nxt][(xq + 0) * XST + xc] = rep2(pxv.x);
            XsD[nxt][(xq + 1) * XST + xc] = rep2(pxv.y);
            XsD[nxt][(xq + 2) * XST + xc] = rep2(pxv.z);
            XsD[nxt][(xq + 3) * XST + xc] = rep2(pxv.w);
        }
        __syncthreads();
        cur ^= 1;
    }

    // ---- degree reduction across 16 ty slices ----
    #pragma unroll
    for (int p = 0; p < 4; p++) {
        int mbase = (p < 2) ? (tx * 4 + p * 2) : (64 + tx * 4 + (p - 2) * 2);
        degS[ty * MT + mbase]     = lo32(dacc[p]);
        degS[ty * MT + mbase + 1] = hi32(dacc[p]);
    }
    __syncthreads();
    if (tid < MT) {
        float sum = 0.0f;
        #pragma unroll
        for (int r = 0; r < KS; r++) sum += degS[r * MT + tid];
        g_deg[((size_t)s * BZv + b) * Mv + m0 + tid] = sum;
    }

    // ---- write raw partials ----
    float* Pb = g_part + (((size_t)s * BZv + b) * Mv + m0) * Cv + ty * 4;
    #pragma unroll
    for (int p = 0; p < 4; p++) {
        int mbase = (p < 2) ? (tx * 4 + p * 2) : (64 + tx * 4 + (p - 2) * 2);
        float4 v0, v1;
        v0.x = lo32(acc[p][0]); v0.y = lo32(acc[p][1]);
        v0.z = lo32(acc[p][2]); v0.w = lo32(acc[p][3]);
        v1.x = hi32(acc[p][0]); v1.y = hi32(acc[p][1]);
        v1.z = hi32(acc[p][2]); v1.w = hi32(acc[p][3]);
        *(float4*)(Pb + (size_t)mbase * Cv)       = v0;
        *(float4*)(Pb + (size_t)(mbase + 1) * Cv) = v1;
    }
}

__global__ __launch_bounds__(256)
void sg_kg_pool_combine(float* __restrict__ out)   // (B, M, C)
{
    int gid = blockIdx.x * blockDim.x + threadIdx.x;   // 0 .. B*M*C/4-1 = 262143
    int c4 = gid & 15;                 // float4 index along C
    int m  = (gid >> 4) & (Mv - 1);
    int b  = gid >> 19;                // gid / (16*2048*... ) -> careful below
    // recompute b safely: per-b chunk = Mv*Cv/4 = 32768
    b = gid / (Mv * Cv / 4);

    size_t base = ((size_t)b * Mv + m) * Cv + c4 * 4;
    const float4 p0 = *(const float4*)(g_part + base);
    const float4 p1 = *(const float4*)(g_part + (size_t)BZv * Mv * Cv + base);
    float d = g_deg[(size_t)b * Mv + m] + g_deg[(size_t)BZv * Mv + (size_t)b * Mv + m];
    float inv = 1.0f / fmaxf(d, 1.0f);
    float4 o;
    o.x = (p0.x + p1.x) * inv;
    o.y = (p0.y + p1.y) * inv;
    o.z = (p0.z + p1.z) * inv;
    o.w = (p0.w + p1.w) * inv;
    *(float4*)(out + base) = o;
}

extern "C" void kernel_launch(void* const* d_in, const int* in_sizes, int n_in,
                              void* d_out, int out_size)
{
    const float* x;
    const float* adj;
    if (in_sizes[0] == BZv * Cv * Nv) {
        x   = (const float*)d_in[0];
        adj = (const float*)d_in[1];
    } else {
        x   = (const float*)d_in[1];
        adj = (const float*)d_in[0];
    }
    float* out = (float*)d_out;

    dim3 grid(Mv / MT, BZv, NSPLIT);   // 16 x 8 x 2 = 256 blocks
    sg_kg_pool_main<<<grid, 256>>>(x, adj);

    int total4 = BZv * Mv * Cv / 4;    // 262144
    sg_kg_pool_combine<<<total4 / 256, 256>>>(out);
}

// round 4
// speedup vs baseline: 1.9540x; 1.9540x over previous
#include <cuda_runtime.h>
#include <cuda_fp16.h>
#include <cstdint>

// SGIntoKGPool via legacy warp-level mma.sync (base PTX features, safe on compute_103).
// out[b,m,c] = (sum_n adj[b,n,m] * x[b,c,n]) / max(sum_n adj[b,n,m], 1)
// B=8, C=64, N=4096, M=2048.
// Numerics: adj -> fp16 (rel err ~2^-12), x -> fp16 hi+lo split (2 GEMMs, residual ~2^-23).
// Degrees accumulated in fp32 during conversion (exact-ish), fused epilogue division.

#define BZv 8
#define Cv  64
#define Nv  4096
#define Mv  2048
#define KT  32
#define NTl (Nv / KT)       // 128 k-tiles

// smem layout (static, 46.6 KB)
#define ASTRIDE 80          // bytes per A row (40 halfs: 32 k + 8 pad)
#define ABYTES  10240       // Ah 64*80 + Al 64*80
#define BSTRIDE 272         // bytes per B row (136 halfs: 128 m + 8 pad)
#define BBYTES  8704        // 32 rows
#define BUFB    (ABYTES + BBYTES)          // 18944
#define OFF_DEGS (2 * BUFB)                // 37888
#define OFF_INVS (OFF_DEGS + 16 * 128 * 4) // 46080
#define SMEMB    (OFF_INVS + 512)          // 46592

// x hi/lo fp16 panels, ldmatrix-ready: per (b, ktile): [Ah 64x40 halfs][Al 64x40 halfs] = 640 uint4
__device__ uint4 g_A[BZv * NTl * 640];

__device__ __forceinline__ uint32_t smem_u32(const void* p) {
    uint32_t a;
    asm("{ .reg .u64 t; cvta.to.shared.u64 t, %1; cvt.u32.u64 %0, t; }" : "=r"(a) : "l"(p));
    return a;
}
__device__ __forceinline__ void ldsm4(uint32_t (&r)[4], uint32_t a) {
    asm volatile("ldmatrix.sync.aligned.m8n8.x4.shared.b16 {%0,%1,%2,%3}, [%4];"
                 : "=r"(r[0]), "=r"(r[1]), "=r"(r[2]), "=r"(r[3]) : "r"(a));
}
__device__ __forceinline__ void ldsm4t(uint32_t (&r)[4], uint32_t a) {
    asm volatile("ldmatrix.sync.aligned.m8n8.x4.trans.shared.b16 {%0,%1,%2,%3}, [%4];"
                 : "=r"(r[0]), "=r"(r[1]), "=r"(r[2]), "=r"(r[3]) : "r"(a));
}
__device__ __forceinline__ void mma16816(float (&d)[4], const uint32_t (&a)[4],
                                         uint32_t b0, uint32_t b1) {
    asm volatile("mma.sync.aligned.m16n8k16.row.col.f32.f16.f16.f32 "
                 "{%0,%1,%2,%3}, {%4,%5,%6,%7}, {%8,%9}, {%0,%1,%2,%3};"
                 : "+f"(d[0]), "+f"(d[1]), "+f"(d[2]), "+f"(d[3])
                 : "r"(a[0]), "r"(a[1]), "r"(a[2]), "r"(a[3]), "r"(b0), "r"(b1));
}
__device__ __forceinline__ unsigned packh2(float v0, float v1) {
    __half h0 = __float2half_rn(v0), h1 = __float2half_rn(v1);
    return (unsigned)__half_as_ushort(h0) | ((unsigned)__half_as_ushort(h1) << 16);
}

// ---------------- prep: x -> fp16 hi/lo panels ----------------
__global__ __launch_bounds__(256)
void prep_A(const float* __restrict__ x) {
    unsigned gid = blockIdx.x * 256 + threadIdx.x;       // 8*128*64*20 = 1,310,720
    if (gid >= (unsigned)(BZv * NTl * Cv * 20)) return;
    unsigned p   = gid % 20;
    unsigned row = (gid / 20) % 64;
    unsigned kt  = (gid / 1280) % NTl;
    unsigned b   = gid / (NTl * Cv * 20);
    float v0 = 0.f, v1 = 0.f;
    if (p < 16) {
        const float* px = x + ((size_t)b * Cv + row) * Nv + kt * KT + p * 2;
        v0 = px[0]; v1 = px[1];
    }
    __half h0 = __float2half_rn(v0), h1 = __float2half_rn(v1);
    float f0 = __half2float(h0), f1 = __half2float(h1);
    unsigned hi = (unsigned)__half_as_ushort(h0) | ((unsigned)__half_as_ushort(h1) << 16);
    unsigned lo = packh2(v0 - f0, v1 - f1);
    unsigned* g32 = (unsigned*)g_A;
    unsigned base = (b * NTl + kt) * 2560;
    g32[base + row * 20 + p] = hi;           // Ah region
    g32[base + 1280 + row * 20 + p] = lo;    // Al region
}

// ---------------- main kernel ----------------
__global__ __launch_bounds__(256, 1)
void sg_kg_hmma(const float* __restrict__ adj, float* __restrict__ out) {
    __shared__ __align__(16) char smem[SMEMB];
    const int tid = threadIdx.x;
    const int lid = tid & 31, wid = tid >> 5;
    const int b = blockIdx.y, m0 = blockIdx.x * 128;
    const int wr = wid & 1;          // M (c) dir: 2 warps
    const int wc = wid >> 1;         // N (m) dir: 4 warps
    const uint32_t sb = smem_u32(smem);

    // conversion lane mapping: thread owns m-granule g (8 m's) x 2 k-rows
    const int g  = tid & 15;
    const int k2 = (tid >> 4) & 1;
    const int kA = wid * 4 + k2 * 2;                 // rows kA, kA+1 of each k-tile

    const float* Ag = adj + (size_t)b * Nv * Mv + (size_t)kA * Mv + m0 + g * 8;
    const uint4* Apan = g_A + (size_t)(b * NTl) * 640;

    float acc[2][4][4];
    #pragma unroll
    for (int i = 0; i < 2; i++)
        #pragma unroll
        for (int j = 0; j < 4; j++)
            #pragma unroll
            for (int q = 0; q < 4; q++) acc[i][j][q] = 0.f;
    float dacc[8] = {0,0,0,0,0,0,0,0};

    // per-thread ldmatrix offsets (within buffer)
    const uint32_t aoff = (uint32_t)((wr * 32 + (lid & 15)) * ASTRIDE + (lid >> 4) * 16);
    const uint32_t boff = (uint32_t)(ABYTES + (lid & 15) * BSTRIDE
                                     + (wc * 32 + (lid >> 4) * 8) * 2);

    float4 f00, f01, f10, f11;       // adj prefetch: 2 rows x 8 floats
    uint4 a0, a1, a2;                // A panel prefetch (640 uint4 / 256 threads)

    // --- stage: deg accumulate + fp16 convert + STS (adj) + A panel copy ---
    auto stage = [&](int bufsel) {
        dacc[0] += f00.x + f10.x; dacc[1] += f00.y + f10.y;
        dacc[2] += f00.z + f10.z; dacc[3] += f00.w + f10.w;
        dacc[4] += f01.x + f11.x; dacc[5] += f01.y + f11.y;
        dacc[6] += f01.z + f11.z; dacc[7] += f01.w + f11.w;
        char* buf = smem + bufsel * BUFB;
        uint4 r0 = make_uint4(packh2(f00.x, f00.y), packh2(f00.z, f00.w),
                              packh2(f01.x, f01.y), packh2(f01.z, f01.w));
        uint4 r1 = make_uint4(packh2(f10.x, f10.y), packh2(f10.z, f10.w),
                              packh2(f11.x, f11.y), packh2(f11.z, f11.w));
        *(uint4*)(buf + ABYTES + kA * BSTRIDE + g * 16)       = r0;
        *(uint4*)(buf + ABYTES + (kA + 1) * BSTRIDE + g * 16) = r1;
        uint4* Ad = (uint4*)buf;
        Ad[tid] = a0; Ad[tid + 256] = a1;
        if (tid < 128) Ad[tid + 512] = a2;
    };

    // prologue: tile 0
    {
        f00 = ((const float4*)Ag)[0];        f01 = ((const float4*)Ag)[1];
        f10 = ((const float4*)(Ag + Mv))[0]; f11 = ((const float4*)(Ag + Mv))[1];
        a0 = Apan[tid]; a1 = Apan[tid + 256];
        if (tid < 128) a2 = Apan[tid + 512];
        stage(0);
        __syncthreads();
    }

    for (int t = 0; t < NTl; t++) {
        if (t + 1 < NTl) {
            const float* Agn = Ag + (size_t)(t + 1) * KT * Mv;
            f00 = ((const float4*)Agn)[0];        f01 = ((const float4*)Agn)[1];
            f10 = ((const float4*)(Agn + Mv))[0]; f11 = ((const float4*)(Agn + Mv))[1];
            const uint4* Ap = Apan + (size_t)(t + 1) * 640;
            a0 = Ap[tid]; a1 = Ap[tid + 256];
            if (tid < 128) a2 = Ap[tid + 512];
        }

        const uint32_t base = sb + (t & 1) * BUFB;
        #pragma unroll
        for (int kb = 0; kb < 2; kb++) {
            uint32_t ah0[4], ah1[4], al0[4], al1[4], b0[4], b1[4];
            const uint32_t ka = base + aoff + kb * 32;          // kb*16 halfs
            ldsm4(ah0, ka);
            ldsm4(ah1, ka + 16 * ASTRIDE);
            ldsm4(al0, ka + 5120);
            ldsm4(al1, ka + 5120 + 16 * ASTRIDE);
            const uint32_t kbb = base + boff + kb * 16 * BSTRIDE;
            ldsm4t(b0, kbb);
            ldsm4t(b1, kbb + 32);                               // +16 m halfs
            // hi GEMM
            mma16816(acc[0][0], ah0, b0[0], b0[1]); mma16816(acc[0][1], ah0, b0[2], b0[3]);
            mma16816(acc[0][2], ah0, b1[0], b1[1]); mma16816(acc[0][3], ah0, b1[2], b1[3]);
            mma16816(acc[1][0], ah1, b0[0], b0[1]); mma16816(acc[1][1], ah1, b0[2], b0[3]);
            mma16816(acc[1][2], ah1, b1[0], b1[1]); mma16816(acc[1][3], ah1, b1[2], b1[3]);
            // lo GEMM (same accumulators)
            mma16816(acc[0][0], al0, b0[0], b0[1]); mma16816(acc[0][1], al0, b0[2], b0[3]);
            mma16816(acc[0][2], al0, b1[0], b1[1]); mma16816(acc[0][3], al0, b1[2], b1[3]);
            mma16816(acc[1][0], al1, b0[0], b0[1]); mma16816(acc[1][1], al1, b0[2], b0[3]);
            mma16816(acc[1][2], al1, b1[0], b1[1]); mma16816(acc[1][3], al1, b1[2], b1[3]);
        }

        if (t + 1 < NTl) stage((t + 1) & 1);
        __syncthreads();
    }

    // ---- degree reduction ----
    float* degS = (float*)(smem + OFF_DEGS);
    float* invS = (float*)(smem + OFF_INVS);
    #pragma unroll
    for (int j = 0; j < 8; j++)
        degS[(tid >> 4) * 128 + g * 8 + j] = dacc[j];

    // ---- stage accumulators to smem (outS aliases buffers; compute is done) ----
    float* outS = (float*)smem;   // [m][c], stride 68 floats
    __syncthreads();
    if (tid < 128) {
        float s = 0.f;
        #pragma unroll
        for (int i = 0; i < 16; i++) s += degS[i * 128 + tid];
        invS[tid] = 1.0f / fmaxf(s, 1.0f);
    }
    #pragma unroll
    for (int mt = 0; mt < 2; mt++) {
        #pragma unroll
        for (int nt = 0; nt < 4; nt++) {
            int c_row = wr * 32 + mt * 16 + (lid >> 2);
            int m_col = wc * 32 + nt * 8 + (lid & 3) * 2;
            outS[m_col * 68 + c_row]             = acc[mt][nt][0];
            outS[(m_col + 1) * 68 + c_row]       = acc[mt][nt][1];
            outS[m_col * 68 + c_row + 8]         = acc[mt][nt][2];
            outS[(m_col + 1) * 68 + c_row + 8]   = acc[mt][nt][3];
        }
    }
    __syncthreads();

    // ---- scaled float4 stores ----
    float* Og = out + ((size_t)b * Mv + m0) * Cv;
    #pragma unroll
    for (int i = 0; i < 8; i++) {
        int idx = tid + i * 256;                 // 2048 float4s
        int ml = idx >> 4, c4 = (idx & 15) * 4;
        float4 v = *(float4*)(outS + ml * 68 + c4);
        float inv = invS[ml];
        v.x *= inv; v.y *= inv; v.z *= inv; v.w *= inv;
        *(float4*)(Og + (size_t)ml * Cv + c4) = v;
    }
}

extern "C" void kernel_launch(void* const* d_in, const int* in_sizes, int n_in,
                              void* d_out, int out_size)
{
    const float* x;
    const float* adj;
    if (in_sizes[0] == BZv * Cv * Nv) {
        x   = (const float*)d_in[0];
        adj = (const float*)d_in[1];
    } else {
        x   = (const float*)d_in[1];
        adj = (const float*)d_in[0];
    }
    float* out = (float*)d_out;

    prep_A<<<(BZv * NTl * Cv * 20 + 255) / 256, 256>>>(x);   // 5120 blocks
    sg_kg_hmma<<<dim3(Mv / 128, BZv), 256>>>(adj, out);
}

// round 5
// speedup vs baseline: 2.0843x; 1.0667x over previous
#include <cuda_runtime.h>
#include <cuda_fp16.h>
#include <cstdint>

// SGIntoKGPool via legacy warp-level mma.sync (base PTX, safe on compute_103).
// out[b,m,c] = (sum_n adj[b,n,m] * x[b,c,n]) / max(sum_n adj[b,n,m], 1)
// B=8, C=64, N=4096, M=2048.
// Round 5: m-tile 64 -> 256 CTAs, 2 CTAs/SM for latency hiding.
// Numerics: adj fp16 (err ~2^-12), x fp16 hi+lo (2 GEMMs), fp32 degrees fused.

#define BZv 8
#define Cv  64
#define Nv  4096
#define Mv  2048
#define KT  32
#define NTl (Nv / KT)       // 128 k-tiles
#define MTm 64              // m-tile

// smem layout (static, ~37 KB)
#define ASTRIDE 80          // bytes per A row (40 halfs: 32 k + 8 pad)
#define ABYTES  10240       // Ah 64*80 + Al 64*80
#define BSTRIDE 144         // bytes per B row (72 halfs: 64 m + 8 pad)
#define BBYTES  4608        // 32 rows
#define BUFB    (ABYTES + BBYTES)          // 14848
#define OFF_DEGS (2 * BUFB)                // 29696
#define OFF_INVS (OFF_DEGS + 32 * 64 * 4)  // 37888
#define SMEMB    (OFF_INVS + 256)          // 38144

// x hi/lo fp16 panels, ldmatrix-ready: per (b, ktile): [Ah 64x40][Al 64x40] halfs = 640 uint4
__device__ uint4 g_A[BZv * NTl * 640];

__device__ __forceinline__ uint32_t smem_u32(const void* p) {
    uint32_t a;
    asm("{ .reg .u64 t; cvta.to.shared.u64 t, %1; cvt.u32.u64 %0, t; }" : "=r"(a) : "l"(p));
    return a;
}
__device__ __forceinline__ void ldsm4(uint32_t (&r)[4], uint32_t a) {
    asm volatile("ldmatrix.sync.aligned.m8n8.x4.shared.b16 {%0,%1,%2,%3}, [%4];"
                 : "=r"(r[0]), "=r"(r[1]), "=r"(r[2]), "=r"(r[3]) : "r"(a));
}
__device__ __forceinline__ void ldsm4t(uint32_t (&r)[4], uint32_t a) {
    asm volatile("ldmatrix.sync.aligned.m8n8.x4.trans.shared.b16 {%0,%1,%2,%3}, [%4];"
                 : "=r"(r[0]), "=r"(r[1]), "=r"(r[2]), "=r"(r[3]) : "r"(a));
}
__device__ __forceinline__ void mma16816(float (&d)[4], const uint32_t (&a)[4],
                                         uint32_t b0, uint32_t b1) {
    asm volatile("mma.sync.aligned.m16n8k16.row.col.f32.f16.f16.f32 "
                 "{%0,%1,%2,%3}, {%4,%5,%6,%7}, {%8,%9}, {%0,%1,%2,%3};"
                 : "+f"(d[0]), "+f"(d[1]), "+f"(d[2]), "+f"(d[3])
                 : "r"(a[0]), "r"(a[1]), "r"(a[2]), "r"(a[3]), "r"(b0), "r"(b1));
}
__device__ __forceinline__ unsigned packh2(float v0, float v1) {
    __half h0 = __float2half_rn(v0), h1 = __float2half_rn(v1);
    return (unsigned)__half_as_ushort(h0) | ((unsigned)__half_as_ushort(h1) << 16);
}

// ---------------- prep: x -> fp16 hi/lo panels ----------------
__global__ __launch_bounds__(256)
void prep_A(const float* __restrict__ x) {
    unsigned gid = blockIdx.x * 256 + threadIdx.x;       // 8*128*64*20 = 1,310,720
    if (gid >= (unsigned)(BZv * NTl * Cv * 20)) return;
    unsigned p   = gid % 20;
    unsigned row = (gid / 20) % 64;
    unsigned kt  = (gid / 1280) % NTl;
    unsigned b   = gid / (NTl * Cv * 20);
    float v0 = 0.f, v1 = 0.f;
    if (p < 16) {
        const float* px = x + ((size_t)b * Cv + row) * Nv + kt * KT + p * 2;
        v0 = px[0]; v1 = px[1];
    }
    __half h0 = __float2half_rn(v0), h1 = __float2half_rn(v1);
    float f0 = __half2float(h0), f1 = __half2float(h1);
    unsigned hi = (unsigned)__half_as_ushort(h0) | ((unsigned)__half_as_ushort(h1) << 16);
    unsigned lo = packh2(v0 - f0, v1 - f1);
    unsigned* g32 = (unsigned*)g_A;
    unsigned base = (b * NTl + kt) * 2560;
    g32[base + row * 20 + p] = hi;           // Ah region
    g32[base + 1280 + row * 20 + p] = lo;    // Al region
}

// ---------------- main kernel ----------------
__global__ __launch_bounds__(256, 2)
void sg_kg_hmma(const float* __restrict__ adj, float* __restrict__ out) {
    __shared__ __align__(16) char smem[SMEMB];
    const int tid = threadIdx.x;
    const int lid = tid & 31, wid = tid >> 5;
    const int b = blockIdx.y, m0 = blockIdx.x * MTm;
    const int wr = wid & 1;          // c dir: 2 warps x 32
    const int wc = wid >> 1;         // m dir: 4 warps x 16
    const uint32_t sb = smem_u32(smem);

    // conversion lane mapping: thread owns row r (k), float4 quads q and q+8 (m)
    const int r = tid >> 3;          // 0..31 (k within tile)
    const int q = tid & 7;           // 0..7

    const float* Ag = adj + (size_t)b * Nv * Mv + (size_t)r * Mv + m0 + q * 4;
    const uint4* Apan = g_A + (size_t)(b * NTl) * 640;

    float acc[2][2][4];
    #pragma unroll
    for (int i = 0; i < 2; i++)
        #pragma unroll
        for (int j = 0; j < 2; j++)
            #pragma unroll
            for (int p = 0; p < 4; p++) acc[i][j][p] = 0.f;
    float dacc[8] = {0,0,0,0,0,0,0,0};

    // per-thread ldmatrix offsets (within buffer)
    const uint32_t aoff = (uint32_t)((wr * 32 + (lid & 15)) * ASTRIDE + (lid >> 4) * 16);
    const uint32_t boff = (uint32_t)(ABYTES + (lid & 15) * BSTRIDE
                                     + (wc * 16 + (lid >> 4) * 8) * 2);

    float4 f0, f1;                   // adj prefetch: row r, m quads q and q+8
    uint4 a0, a1, a2;                // A panel prefetch (640 uint4 / 256 threads)

    // --- stage: deg accumulate + fp16 convert + STS ---
    auto stage = [&](int bufsel) {
        dacc[0] += f0.x; dacc[1] += f0.y; dacc[2] += f0.z; dacc[3] += f0.w;
        dacc[4] += f1.x; dacc[5] += f1.y; dacc[6] += f1.z; dacc[7] += f1.w;
        char* buf = smem + bufsel * BUFB;
        uint2 w0 = make_uint2(packh2(f0.x, f0.y), packh2(f0.z, f0.w));
        uint2 w1 = make_uint2(packh2(f1.x, f1.y), packh2(f1.z, f1.w));
        *(uint2*)(buf + ABYTES + r * BSTRIDE + q * 8)      = w0;
        *(uint2*)(buf + ABYTES + r * BSTRIDE + q * 8 + 64) = w1;
        uint4* Ad = (uint4*)buf;
        Ad[tid] = a0; Ad[tid + 256] = a1;
        if (tid < 128) Ad[tid + 512] = a2;
    };

    // prologue: tile 0
    {
        f0 = *(const float4*)Ag;
        f1 = *(const float4*)(Ag + 32);
        a0 = Apan[tid]; a1 = Apan[tid + 256];
        if (tid < 128) a2 = Apan[tid + 512];
        stage(0);
        __syncthreads();
    }

    for (int t = 0; t < NTl; t++) {
        if (t + 1 < NTl) {
            const float* Agn = Ag + (size_t)(t + 1) * KT * Mv;
            f0 = *(const float4*)Agn;
            f1 = *(const float4*)(Agn + 32);
            const uint4* Ap = Apan + (size_t)(t + 1) * 640;
            a0 = Ap[tid]; a1 = Ap[tid + 256];
            if (tid < 128) a2 = Ap[tid + 512];
        }

        const uint32_t base = sb + (t & 1) * BUFB;
        #pragma unroll
        for (int kb = 0; kb < 2; kb++) {
            uint32_t ah0[4], ah1[4], al0[4], al1[4], bb[4];
            const uint32_t ka = base + aoff + kb * 32;          // +16 k halfs
            ldsm4(ah0, ka);
            ldsm4(ah1, ka + 16 * ASTRIDE);
            ldsm4(al0, ka + 5120);
            ldsm4(al1, ka + 5120 + 16 * ASTRIDE);
            ldsm4t(bb, base + boff + kb * 16 * BSTRIDE);
            // hi GEMM
            mma16816(acc[0][0], ah0, bb[0], bb[1]); mma16816(acc[0][1], ah0, bb[2], bb[3]);
            mma16816(acc[1][0], ah1, bb[0], bb[1]); mma16816(acc[1][1], ah1, bb[2], bb[3]);
            // lo GEMM (same accumulators)
            mma16816(acc[0][0], al0, bb[0], bb[1]); mma16816(acc[0][1], al0, bb[2], bb[3]);
            mma16816(acc[1][0], al1, bb[0], bb[1]); mma16816(acc[1][1], al1, bb[2], bb[3]);
        }

        if (t + 1 < NTl) stage((t + 1) & 1);
        __syncthreads();
    }

    // ---- degree reduction: degS[r][m], sum over 32 k-rows ----
    float* degS = (float*)(smem + OFF_DEGS);
    float* invS = (float*)(smem + OFF_INVS);
    #pragma unroll
    for (int j = 0; j < 4; j++) {
        degS[r * 64 + q * 4 + j]      = dacc[j];
        degS[r * 64 + q * 4 + 32 + j] = dacc[4 + j];
    }
    __syncthreads();
    if (tid < MTm) {
        float s = 0.f;
        #pragma unroll
        for (int i = 0; i < 32; i++) s += degS[i * 64 + tid];
        invS[tid] = 1.0f / fmaxf(s, 1.0f);
    }

    // ---- stage accumulators to smem (aliases buffers; compute done) ----
    float* outS = (float*)smem;   // [m][c], stride 68 floats (17.4 KB)
    #pragma unroll
    for (int mt = 0; mt < 2; mt++) {
        #pragma unroll
        for (int nt = 0; nt < 2; nt++) {
            int c_row = wr * 32 + mt * 16 + (lid >> 2);
            int m_col = wc * 16 + nt * 8 + (lid & 3) * 2;
            outS[m_col * 68 + c_row]           = acc[mt][nt][0];
            outS[(m_col + 1) * 68 + c_row]     = acc[mt][nt][1];
            outS[m_col * 68 + c_row + 8]       = acc[mt][nt][2];
            outS[(m_col + 1) * 68 + c_row + 8] = acc[mt][nt][3];
        }
    }
    __syncthreads();

    // ---- scaled float4 stores ----
    float* Og = out + ((size_t)b * Mv + m0) * Cv;
    #pragma unroll
    for (int i = 0; i < 4; i++) {
        int idx = tid + i * 256;                 // 1024 float4s
        int ml = idx >> 4, c4 = (idx & 15) * 4;
        float4 v = *(float4*)(outS + ml * 68 + c4);
        float inv = invS[ml];
        v.x *= inv; v.y *= inv; v.z *= inv; v.w *= inv;
        *(float4*)(Og + (size_t)ml * Cv + c4) = v;
    }
}

extern "C" void kernel_launch(void* const* d_in, const int* in_sizes, int n_in,
                              void* d_out, int out_size)
{
    const float* x;
    const float* adj;
    if (in_sizes[0] == BZv * Cv * Nv) {
        x   = (const float*)d_in[0];
        adj = (const float*)d_in[1];
    } else {
        x   = (const float*)d_in[1];
        adj = (const float*)d_in[0];
    }
    float* out = (float*)d_out;

    prep_A<<<(BZv * NTl * Cv * 20 + 255) / 256, 256>>>(x);   // 5120 blocks
    sg_kg_hmma<<<dim3(Mv / MTm, BZv), 256>>>(adj, out);      // 32 x 8 = 256 CTAs
}

// round 6
// speedup vs baseline: 2.2276x; 1.0688x over previous
#include <cuda_runtime.h>
#include <cuda_fp16.h>
#include <cstdint>

// SGIntoKGPool via legacy warp-level mma.sync (base PTX, safe on compute_103).
// out[b,m,c] = (sum_n adj[b,n,m] * x[b,c,n]) / max(sum_n adj[b,n,m], 1)
// B=8, C=64, N=4096, M=2048.
// Round 6: x hi/lo panels stored in MMA *fragment order* -> A operands loaded
// directly from global (L2-resident), no A smem staging / ldmatrix. Only adj
// is staged through smem (fp32 LDG -> fp16 convert -> STS -> ldmatrix.trans).

#define BZv 8
#define Cv  64
#define Nv  4096
#define Mv  2048
#define KT  32
#define NTl (Nv / KT)       // 128 k-tiles
#define MTm 64              // m-tile

// smem: B double buffer + degree scratch + epilogue staging (aliased)
#define BSTRIDE 144          // bytes per B row (72 halfs: 64 m + 8 pad)
#define BBYTES  4608         // 32 rows
#define OFF_DEGS (2 * BBYTES)               // 9216  (32*64*4 = 8192 bytes)
#define OFF_INVS 17408                      // 256 bytes (after outS region)
#define SMEMB    (OFF_INVS + 256)           // 17664

// x hi/lo fp16 fragment panels: per (b,kt): 16 groups x 32 lanes x uint4 = 8KB
// group = hilo*8 + cblk*2 + kb   (cblk: 16-row c block 0..3, kb: k half 0..1)
__device__ uint4 g_A[BZv * NTl * 512];      // 8 MB

__device__ __forceinline__ uint32_t smem_u32(const void* p) {
    uint32_t a;
    asm("{ .reg .u64 t; cvta.to.shared.u64 t, %1; cvt.u32.u64 %0, t; }" : "=r"(a) : "l"(p));
    return a;
}
__device__ __forceinline__ void ldsm4t(uint32_t (&r)[4], uint32_t a) {
    asm volatile("ldmatrix.sync.aligned.m8n8.x4.trans.shared.b16 {%0,%1,%2,%3}, [%4];"
                 : "=r"(r[0]), "=r"(r[1]), "=r"(r[2]), "=r"(r[3]) : "r"(a));
}
__device__ __forceinline__ void mma16816(float (&d)[4], const uint4& a,
                                         uint32_t b0, uint32_t b1) {
    asm volatile("mma.sync.aligned.m16n8k16.row.col.f32.f16.f16.f32 "
                 "{%0,%1,%2,%3}, {%4,%5,%6,%7}, {%8,%9}, {%0,%1,%2,%3};"
                 : "+f"(d[0]), "+f"(d[1]), "+f"(d[2]), "+f"(d[3])
                 : "r"(a.x), "r"(a.y), "r"(a.z), "r"(a.w), "r"(b0), "r"(b1));
}
__device__ __forceinline__ unsigned packh2(float v0, float v1) {
    __half h0 = __float2half_rn(v0), h1 = __float2half_rn(v1);
    return (unsigned)__half_as_ushort(h0) | ((unsigned)__half_as_ushort(h1) << 16);
}
__device__ __forceinline__ unsigned pack_hl(float a, float b, unsigned& lo) {
    __half ha = __float2half_rn(a), hb = __float2half_rn(b);
    lo = packh2(a - __half2float(ha), b - __half2float(hb));
    return (unsigned)__half_as_ushort(ha) | ((unsigned)__half_as_ushort(hb) << 16);
}

// ---------------- prep: x -> fp16 hi/lo fragment panels ----------------
// thread <-> (b, kt, cblk, kb, lid): 8*128*4*2*32 = 262144 threads
__global__ __launch_bounds__(256)
void prep_A(const float* __restrict__ x) {
    unsigned gid  = blockIdx.x * 256 + threadIdx.x;
    unsigned lid  = gid & 31;
    unsigned kb   = (gid >> 5) & 1;
    unsigned cblk = (gid >> 6) & 3;
    unsigned kt   = (gid >> 8) & (NTl - 1);
    unsigned b    = gid >> 15;

    int r0 = cblk * 16 + (lid >> 2);         // c row (0..63)
    int k0 = kb * 16 + (lid & 3) * 2;        // k within tile
    const float* px = x + ((size_t)b * Cv + r0) * Nv + kt * KT + k0;

    float v00 = px[0],           v01 = px[1];
    float v10 = px[8 * Nv],      v11 = px[8 * Nv + 1];
    float v02 = px[8],           v03 = px[9];
    float v12 = px[8 * Nv + 8],  v13 = px[8 * Nv + 9];

    uint4 hi, lo;
    hi.x = pack_hl(v00, v01, lo.x);
    hi.y = pack_hl(v10, v11, lo.y);
    hi.z = pack_hl(v02, v03, lo.z);
    hi.w = pack_hl(v12, v13, lo.w);

    size_t base = ((size_t)(b * NTl + kt) << 9) + lid;
    g_A[base + (size_t)(cblk * 2 + kb) * 32]       = hi;
    g_A[base + (size_t)(8 + cblk * 2 + kb) * 32]   = lo;
}

// ---------------- main kernel ----------------
__global__ __launch_bounds__(256, 2)
void sg_kg_hmma(const float* __restrict__ adj, float* __restrict__ out) {
    __shared__ __align__(16) char smem[SMEMB];
    const int tid = threadIdx.x;
    const int lid = tid & 31, wid = tid >> 5;
    const int b = blockIdx.y, m0 = blockIdx.x * MTm;
    const int wr = wid & 1;          // c dir: 2 warps x 32 rows
    const int wc = wid >> 1;         // m dir: 4 warps x 16 cols
    const uint32_t sb = smem_u32(smem);

    // adj conversion lane mapping: thread owns k-row r, m float4-quads q, q+8
    const int r = tid >> 3;          // 0..31
    const int q = tid & 7;           // 0..7

    const float* Ag = adj + (size_t)b * Nv * Mv + (size_t)r * Mv + m0 + q * 4;

    float acc[2][2][4];
    #pragma unroll
    for (int i = 0; i < 2; i++)
        #pragma unroll
        for (int j = 0; j < 2; j++)
            #pragma unroll
            for (int p = 0; p < 4; p++) acc[i][j][p] = 0.f;
    float dacc[8] = {0,0,0,0,0,0,0,0};

    // per-thread B ldmatrix offset (within one B buffer)
    const uint32_t boff = (uint32_t)((lid & 15) * BSTRIDE
                                     + (wc * 16 + (lid >> 4) * 8) * 2);

    // A fragment group indices for this warp (uint4 strides of 32)
    const int gh0 = (wr * 4 + 0) * 32, gh1 = (wr * 4 + 2) * 32;       // kb=0 hi
    const int gh2 = (wr * 4 + 1) * 32, gh3 = (wr * 4 + 3) * 32;       // kb=1 hi
    const int gl0 = (8 + wr * 4 + 0) * 32, gl1 = (8 + wr * 4 + 2) * 32;
    const int gl2 = (8 + wr * 4 + 1) * 32, gl3 = (8 + wr * 4 + 3) * 32;

    float4 f0, f1;        // adj prefetch
    uint4 afrag[8];       // A fragments for current tile

    auto loadA = [&](int t) {
        const uint4* At = g_A + ((size_t)(b * NTl + t) << 9) + lid;
        afrag[0] = At[gh0]; afrag[1] = At[gh1];
        afrag[2] = At[gl0]; afrag[3] = At[gl1];
        afrag[4] = At[gh2]; afrag[5] = At[gh3];
        afrag[6] = At[gl2]; afrag[7] = At[gl3];
    };
    auto stageB = [&](int bufsel) {
        dacc[0] += f0.x; dacc[1] += f0.y; dacc[2] += f0.z; dacc[3] += f0.w;
        dacc[4] += f1.x; dacc[5] += f1.y; dacc[6] += f1.z; dacc[7] += f1.w;
        char* buf = smem + bufsel * BBYTES;
        uint2 w0 = make_uint2(packh2(f0.x, f0.y), packh2(f0.z, f0.w));
        uint2 w1 = make_uint2(packh2(f1.x, f1.y), packh2(f1.z, f1.w));
        *(uint2*)(buf + r * BSTRIDE + q * 8)      = w0;
        *(uint2*)(buf + r * BSTRIDE + q * 8 + 64) = w1;
    };

    // prologue: tile 0
    {
        f0 = *(const float4*)Ag;
        f1 = *(const float4*)(Ag + 32);
        loadA(0);
        stageB(0);
        __syncthreads();
    }

    for (int t = 0; t < NTl; t++) {
        if (t + 1 < NTl) {
            const float* Agn = Ag + (size_t)(t + 1) * KT * Mv;
            f0 = *(const float4*)Agn;
            f1 = *(const float4*)(Agn + 32);
        }

        const uint32_t base = sb + (t & 1) * BBYTES;
        {
            uint32_t bb[4];
            ldsm4t(bb, base + boff);                       // kb = 0
            mma16816(acc[0][0], afrag[0], bb[0], bb[1]);
            mma16816(acc[0][1], afrag[0], bb[2], bb[3]);
            mma16816(acc[1][0], afrag[1], bb[0], bb[1]);
            mma16816(acc[1][1], afrag[1], bb[2], bb[3]);
            mma16816(acc[0][0], afrag[2], bb[0], bb[1]);
            mma16816(acc[0][1], afrag[2], bb[2], bb[3]);
            mma16816(acc[1][0], afrag[3], bb[0], bb[1]);
            mma16816(acc[1][1], afrag[3], bb[2], bb[3]);
        }
        {
            uint32_t bb[4];
            ldsm4t(bb, base + boff + 16 * BSTRIDE);        // kb = 1
            mma16816(acc[0][0], afrag[4], bb[0], bb[1]);
            mma16816(acc[0][1], afrag[4], bb[2], bb[3]);
            mma16816(acc[1][0], afrag[5], bb[0], bb[1]);
            mma16816(acc[1][1], afrag[5], bb[2], bb[3]);
            mma16816(acc[0][0], afrag[6], bb[0], bb[1]);
            mma16816(acc[0][1], afrag[6], bb[2], bb[3]);
            mma16816(acc[1][0], afrag[7], bb[0], bb[1]);
            mma16816(acc[1][1], afrag[7], bb[2], bb[3]);
        }

        if (t + 1 < NTl) {
            loadA(t + 1);          // L2-resident, lands before next tile's MMAs
            stageB((t + 1) & 1);
        }
        __syncthreads();
    }

    // ---- degree reduction: degS[r][m], sum over 32 k-rows ----
    float* degS = (float*)(smem + OFF_DEGS);
    float* invS = (float*)(smem + OFF_INVS);
    #pragma unroll
    for (int j = 0; j < 4; j++) {
        degS[r * 64 + q * 4 + j]      = dacc[j];
        degS[r * 64 + q * 4 + 32 + j] = dacc[4 + j];
    }
    __syncthreads();
    if (tid < MTm) {
        float s = 0.f;
        #pragma unroll
        for (int i = 0; i < 32; i++) s += degS[i * 64 + tid];
        invS[tid] = 1.0f / fmaxf(s, 1.0f);
    }
    __syncthreads();   // degS fully read before outS overwrites it

    // ---- stage accumulators to smem (aliases buffers+degS; compute done) ----
    float* outS = (float*)smem;   // [m][c], stride 68 floats (17408 B)
    #pragma unroll
    for (int mt = 0; mt < 2; mt++) {
        #pragma unroll
        for (int nt = 0; nt < 2; nt++) {
            int c_row = wr * 32 + mt * 16 + (lid >> 2);
            int m_col = wc * 16 + nt * 8 + (lid & 3) * 2;
            outS[m_col * 68 + c_row]           = acc[mt][nt][0];
            outS[(m_col + 1) * 68 + c_row]     = acc[mt][nt][1];
            outS[m_col * 68 + c_row + 8]       = acc[mt][nt][2];
            outS[(m_col + 1) * 68 + c_row + 8] = acc[mt][nt][3];
        }
    }
    __syncthreads();

    // ---- scaled float4 stores ----
    float* Og = out + ((size_t)b * Mv + m0) * Cv;
    #pragma unroll
    for (int i = 0; i < 4; i++) {
        int idx = tid + i * 256;                 // 1024 float4s
        int ml = idx >> 4, c4 = (idx & 15) * 4;
        float4 v = *(float4*)(outS + ml * 68 + c4);
        float inv = invS[ml];
        v.x *= inv; v.y *= inv; v.z *= inv; v.w *= inv;
        *(float4*)(Og + (size_t)ml * Cv + c4) = v;
    }
}

extern "C" void kernel_launch(void* const* d_in, const int* in_sizes, int n_in,
                              void* d_out, int out_size)
{
    const float* x;
    const float* adj;
    if (in_sizes[0] == BZv * Cv * Nv) {
        x   = (const float*)d_in[0];
        adj = (const float*)d_in[1];
    } else {
        x   = (const float*)d_in[1];
        adj = (const float*)d_in[0];
    }
    float* out = (float*)d_out;

    prep_A<<<1024, 256>>>(x);                                // 262144 threads
    sg_kg_hmma<<<dim3(Mv / MTm, BZv), 256>>>(adj, out);      // 32 x 8 = 256 CTAs
}